// round 4
// baseline (speedup 1.0000x reference)
#include <cuda_runtime.h>
#include <cuda_bf16.h>

#define NTOK 32768
#define DIM  512
#define NEMB 512
#define BM   128            // tokens per block tile
#define BK   64             // embeddings per block tile -> 8 k-tiles
#define BD   16             // d-values per pipeline stage
#define PITCH 18            // floats per smem row: 8B-aligned rows, conflict-free LDS.64
#define NSTAGE (DIM / BD)   // 32

__device__ float g_S[NEMB];   // reference's axis=0 quirk: sum_i emb[i][k]^2

// ---------------------------------------------------------------------------
// Kernel 1: column sum-of-squares of embeddings
// ---------------------------------------------------------------------------
__global__ void col_sumsq_kernel(const float* __restrict__ emb) {
    int c  = blockIdx.x * 32 + (threadIdx.x & 31);
    int r0 = threadIdx.x >> 5;
    float s = 0.f;
    for (int i = r0; i < NEMB; i += 8) {
        float v = emb[i * DIM + c];
        s = fmaf(v, v, s);
    }
    __shared__ float sh[8][32];
    sh[r0][threadIdx.x & 31] = s;
    __syncthreads();
    if (threadIdx.x < 32) {
        float t = 0.f;
        #pragma unroll
        for (int r = 0; r < 8; r++) t += sh[r][threadIdx.x];
        g_S[blockIdx.x * 32 + threadIdx.x] = t;
    }
}

// ---------------------------------------------------------------------------
// PTX helpers
// ---------------------------------------------------------------------------
__device__ __forceinline__ void ffma2(unsigned long long& d,
                                      unsigned long long a, unsigned long long b) {
    asm("fma.rn.f32x2 %0, %1, %2, %0;" : "+l"(d) : "l"(a), "l"(b));
}
__device__ __forceinline__ void cp8(unsigned smem_addr, const float* g) {
    asm volatile("cp.async.ca.shared.global [%0], [%1], 8;" :: "r"(smem_addr), "l"(g));
}
__device__ __forceinline__ void cp_commit() {
    asm volatile("cp.async.commit_group;");
}
template<int N> __device__ __forceinline__ void cp_wait() {
    asm volatile("cp.async.wait_group %0;" :: "n"(N));
}

// ---------------------------------------------------------------------------
// Kernel 2: fused GEMM + argmin + gather.
// 256 threads, 2 CTAs/SM. Tile 128 tok x 64 emb, 8 k-tiles.
// FFMA2 pairs along d: acc.lo = even-d partial, acc.hi = odd-d partial.
// Thread tile: 8 tok (t = ty+16u) x 4 emb (e = tx+16v) -> acc[8][4] = 64 regs.
// smem natural row-major, filled by cp.async (no transposes, no dup-MOVs).
// a-loads broadcast (2 addrs/warp); b-loads conflict-free (18*tx mod 32 even-bank cover).
// ---------------------------------------------------------------------------
__global__ __launch_bounds__(256, 2) void vq_kernel(
    const float* __restrict__ x, const float* __restrict__ emb,
    float* __restrict__ out)
{
    __shared__ __align__(16) float As[2][BM * PITCH];   // 18.4 KB
    __shared__ __align__(16) float Bs[2][BK * PITCH];   //  9.2 KB
    __shared__ float xn_sm[BM];
    __shared__ int   sidx[BM];

    const int tid  = threadIdx.x;
    const int tx   = tid & 15;
    const int ty   = tid >> 4;
    const int lane = tid & 31;
    const int w    = tid >> 5;
    const int tok0 = blockIdx.x * BM;

    // --- per-token squared norm (one warp per token, coalesced float4) ---
    for (int t = w; t < BM; t += 8) {
        const float4* px = (const float4*)(x + (size_t)(tok0 + t) * DIM);
        float s = 0.f;
        #pragma unroll
        for (int j = 0; j < 4; j++) {
            float4 v = px[lane + 32 * j];
            s = fmaf(v.x, v.x, s); s = fmaf(v.y, v.y, s);
            s = fmaf(v.z, v.z, s); s = fmaf(v.w, v.w, s);
        }
        #pragma unroll
        for (int off = 16; off >= 1; off >>= 1)
            s += __shfl_xor_sync(0xffffffffu, s, off);
        if (lane == 0) xn_sm[t] = s;
    }
    // published by the first __syncthreads inside the stage loop

    float bestv[8];
    int   besti[8];
    #pragma unroll
    for (int u = 0; u < 8; u++) { bestv[u] = 3.4e38f; besti[u] = 0; }

    // cp.async addressing: 8B chunk c8 within a BD=16 row, row r0 strided by 32
    const int c8 = tid & 7;       // chunk 0..7
    const int r0 = tid >> 3;      // row 0..31
    const unsigned sA0 = (unsigned)__cvta_generic_to_shared(&As[0][0]);
    const unsigned sB0 = (unsigned)__cvta_generic_to_shared(&Bs[0][0]);
    const unsigned rowoff = (unsigned)(r0 * PITCH + 2 * c8) * 4u;
    const float* gxA = x + (size_t)(tok0 + r0) * DIM + 2 * c8;   // +i*32*DIM, i<4

    for (int kt = 0; kt < NEMB; kt += BK) {
        unsigned long long acc[8][4];
        #pragma unroll
        for (int u = 0; u < 8; u++)
            #pragma unroll
            for (int v = 0; v < 4; v++) acc[u][v] = 0ull;

        const float* gxB = emb + (size_t)(kt + r0) * DIM + 2 * c8;  // +i*32*DIM, i<2

        // preload stage 0 into buf 0
        #pragma unroll
        for (int i = 0; i < 4; i++)
            cp8(sA0 + rowoff + i * (32 * PITCH * 4), gxA + i * (32 * DIM));
        #pragma unroll
        for (int i = 0; i < 2; i++)
            cp8(sB0 + rowoff + i * (32 * PITCH * 4), gxB + i * (32 * DIM));
        cp_commit();

        for (int s = 0; s < NSTAGE; s++) {
            const int buf = s & 1;
            if (s + 1 < NSTAGE) {
                // refill the other buffer (freed by the barrier at end of stage s-1)
                const unsigned oA = (unsigned)(((s + 1) & 1) * BM * PITCH * 4);
                const unsigned oB = (unsigned)(((s + 1) & 1) * BK * PITCH * 4);
                const int d0 = (s + 1) * BD;
                #pragma unroll
                for (int i = 0; i < 4; i++)
                    cp8(sA0 + oA + rowoff + i * (32 * PITCH * 4), gxA + d0 + i * (32 * DIM));
                #pragma unroll
                for (int i = 0; i < 2; i++)
                    cp8(sB0 + oB + rowoff + i * (32 * PITCH * 4), gxB + d0 + i * (32 * DIM));
                cp_commit();
                cp_wait<1>();     // stage s fully landed
            } else {
                cp_wait<0>();
            }
            __syncthreads();

            const float* A  = As[buf];
            const float* Bp = Bs[buf];
            #pragma unroll
            for (int j = 0; j < BD / 2; j++) {
                unsigned long long a[8], b[4];
                #pragma unroll
                for (int u = 0; u < 8; u++)
                    a[u] = *(const unsigned long long*)(A + (ty + 16 * u) * PITCH + 2 * j);
                #pragma unroll
                for (int v = 0; v < 4; v++)
                    b[v] = *(const unsigned long long*)(Bp + (tx + 16 * v) * PITCH + 2 * j);
                #pragma unroll
                for (int u = 0; u < 8; u++)
                    #pragma unroll
                    for (int v = 0; v < 4; v++)
                        ffma2(acc[u][v], a[u], b[v]);
            }
            __syncthreads();   // release buf for refill at stage s+2
        }

        // --- epilogue: reference-identical rounding, running argmin ---
        #pragma unroll
        for (int v = 0; v < 4; v++) {          // v ascending => k ascending (first-min wins)
            const int kk = kt + tx + 16 * v;
            const float Sv = g_S[kk];
            #pragma unroll
            for (int u = 0; u < 8; u++) {
                float lo  = __uint_as_float((unsigned)(acc[u][v] & 0xffffffffull));
                float hi  = __uint_as_float((unsigned)(acc[u][v] >> 32));
                float sim = lo + hi;
                // d = fl( fl(xnorm + S[k]) - 2*sim ); 2*sim exact -> fused ok
                float d = __fmaf_rn(-2.f, sim, xn_sm[ty + 16 * u] + Sv);
                if (d < bestv[u]) { bestv[u] = d; besti[u] = kk; }
            }
        }
    }

    // --- cross-lane argmin over the 16 tx lanes (tie -> smaller index) ---
    #pragma unroll
    for (int u = 0; u < 8; u++) {
        float v = bestv[u]; int idx = besti[u];
        #pragma unroll
        for (int off = 8; off >= 1; off >>= 1) {
            float ov = __shfl_xor_sync(0xffffffffu, v, off);
            int   oi = __shfl_xor_sync(0xffffffffu, idx, off);
            if (ov < v || (ov == v && oi < idx)) { v = ov; idx = oi; }
        }
        if (tx == 0) sidx[ty + 16 * u] = idx;
    }
    __syncthreads();

    // --- fused gather: out[token] = emb[sidx[token]] (emb rows L2-hot) ---
    #pragma unroll 4
    for (int r = w; r < BM; r += 8) {
        const int k = sidx[r];
        const float4* src = (const float4*)(emb + (size_t)k * DIM);
        float4*       dst = (float4*)(out + (size_t)(tok0 + r) * DIM);
        #pragma unroll
        for (int j = 0; j < 4; j++)
            dst[lane + 32 * j] = src[lane + 32 * j];
    }
}

// ---------------------------------------------------------------------------
extern "C" void kernel_launch(void* const* d_in, const int* in_sizes, int n_in,
                              void* d_out, int out_size) {
    const float* x   = (const float*)d_in[0];   // [32768, 512] fp32
    const float* emb = (const float*)d_in[1];   // [512, 512] fp32
    float* out = (float*)d_out;

    col_sumsq_kernel<<<16, 256>>>(emb);
    vq_kernel<<<NTOK / BM, 256>>>(x, emb, out);
}